// round 2
// baseline (speedup 1.0000x reference)
#include <cuda_runtime.h>
#include <math.h>

#define NROWS 4096
#define DIM 512

// ---------------- descriptors ----------------
struct ERole { int enabled; int src; int e; int op; float w; };
struct GemmDesc {
  int enabled, nterms, mul;
  int srcA[3];
  int wKind[3], wIdx[3];
  int bKind, bIdx;
  int actCode;          // 0 none, 1 relu, 2 gelu
  int resBuf, dstBuf;
  float scale;
};

__device__ ERole    g_erole[8][3];
__device__ GemmDesc g_gd[8][7];
__device__ int      g_node_act[8];
__device__ float    g_node_aw[8];
__device__ int      g_rem_mask;

// ---------------- big scratch buffers (device .bss) ----------------
__device__ float g_outbuf[8][NROWS*DIM]; // node outputs (64MB)
__device__ float g_qkv[3][NROWS*DIM];    // q,k,v edge outputs
__device__ float g_prep[3][NROWS*DIM];   // normalized/copied edge inputs
__device__ float g_tt[3][NROWS*DIM];     // node projection temporaries
__device__ float g_lnq[NROWS*DIM];       // LN(q) for MHA
__device__ float g_attn[NROWS*DIM];      // attention output

// buffer id map: 0 inpute, 1 inputo, 2..9 g_outbuf[0..7], 10..12 g_qkv,
// 13..15 g_prep, 16..18 g_tt, 19 g_lnq, 20 g_attn
__device__ __forceinline__ const float* bufPtrC(int id, const float* inpute, const float* inputo){
  if(id==0) return inpute;
  if(id==1) return inputo;
  if(id<10) return g_outbuf[id-2];
  if(id<13) return g_qkv[id-10];
  if(id<16) return g_prep[id-13];
  if(id<19) return g_tt[id-16];
  if(id==19) return g_lnq;
  return g_attn;
}
__device__ __forceinline__ float* bufPtrM(int id){
  if(id<10) return g_outbuf[id-2];
  if(id<13) return g_qkv[id-10];
  if(id<16) return g_prep[id-13];
  if(id<19) return g_tt[id-16];
  if(id==19) return g_lnq;
  return g_attn;
}

__device__ __forceinline__ float geluf(float x){
  float inner = 0.7978845608028654f*(x + 0.044715f*x*x*x);
  return 0.5f*x*(1.f+tanhf(inner));
}
__device__ __forceinline__ float sigmoidf(float x){ return 1.f/(1.f+expf(-x)); }

__device__ __forceinline__ float blockReduceSum(float v){
  __shared__ float red[32];
  int lane = threadIdx.x & 31, w = threadIdx.x >> 5;
  #pragma unroll
  for(int o=16;o;o>>=1) v += __shfl_xor_sync(0xffffffffu, v, o);
  if(lane==0) red[w]=v;
  __syncthreads();
  if(w==0){
    float x = (lane < (int)(blockDim.x>>5)) ? red[lane] : 0.f;
    #pragma unroll
    for(int o=16;o;o>>=1) x += __shfl_xor_sync(0xffffffffu, x, o);
    if(lane==0) red[0]=x;
  }
  __syncthreads();
  float r = red[0];
  __syncthreads();
  return r;
}

// ---------------- routing ----------------
__device__ void selrange(const float* p, int lo, int hi, int& sel, float& w){
  int bi=lo; float bv=p[lo];
  for(int i=lo+1;i<hi;i++) if(p[i]>bv){bv=p[i];bi=i;}
  float s=0.f;
  for(int i=lo;i<hi;i++) s += expf(p[i]-bv);
  sel=bi; w=1.f/s;  // exp(p[bi]-max)==1
}

__device__ void fillRole(int c,int role,int sel,float w,int lind,int snode,int& processed,int computeEnabled){
  int se = sel/5, op = sel%5;
  int inn = (se==0)? -2 : snode+se;
  if(inn>=0) processed |= (1<<inn);
  int src = (inn==-2)?0 : ((inn==-1)?1 : (2+inn));
  ERole er; er.enabled=computeEnabled; er.src=src; er.e=lind+se; er.op=op; er.w=w;
  g_erole[c][role]=er;
}

__device__ void setGemm(int c,int slot,int src0,int wKind0,int wIdx0,int bKind,int bIdx,
                        int actCode,int resBuf,int dstBuf,float scale){
  GemmDesc gd;
  gd.enabled=1; gd.nterms=1; gd.mul=0;
  gd.srcA[0]=src0; gd.srcA[1]=0; gd.srcA[2]=0;
  gd.wKind[0]=wKind0; gd.wIdx[0]=wIdx0;
  gd.wKind[1]=0; gd.wIdx[1]=0; gd.wKind[2]=0; gd.wIdx[2]=0;
  gd.bKind=bKind; gd.bIdx=bIdx;
  gd.actCode=actCode; gd.resBuf=resBuf; gd.dstBuf=dstBuf; gd.scale=scale;
  g_gd[c][slot]=gd;
}

__global__ void route_kernel(const float* __restrict__ node_p, const float* __restrict__ edge_p){
  if(threadIdx.x!=0 || blockIdx.x!=0) return;
  int processed = 0;
  int lind = 0;
  for(int c=0;c<8;c++){
    for(int s=0;s<7;s++) g_gd[c][s].enabled=0;
    for(int r=0;r<3;r++) g_erole[c][r].enabled=0;

    int nsrc = (c+2<5)? c+2 : 5;
    int snode = c - nsrc;
    int L = nsrc*5;
    const float* ep0 = edge_p + lind*5;
    const float* ep1 = edge_p + 170 + lind*5;
    const float* ep2 = edge_p + 340 + lind*5;
    const float* np  = node_p + c*8;

    int act=0; { float b=np[0]; for(int i=1;i<8;i++) if(np[i]>b){b=np[i];act=i;} }
    float aw;
    { float m=np[0]; for(int i=1;i<8;i++) m=fmaxf(m,np[i]);
      float s=0.f; for(int i=0;i<8;i++) s+=expf(np[i]-m);
      aw = expf(np[act]-m)/s; }
    g_node_act[c]=act; g_node_aw[c]=aw;

    // q: mask first 5 (encoder source masked for q)
    int qsel; float qw;
    selrange(ep0, 5, L, qsel, qw);
    fillRole(c,0,qsel,qw,lind,snode,processed,1);

    // k (act<7): mask first 5 iff act>0
    int ksel = -1;
    if(act<7){
      int lo = (act>0)?5:0;
      float kw;
      selrange(ep1, lo, L, ksel, kw);
      fillRole(c,1,ksel,kw,lind,snode,processed,1);
    }
    // v (act<5)
    if(act<5){
      int vsel; float vw;
      if(act==0 && (ksel/5)==0){
        selrange(ep2, 0, 5, vsel, vw);           // first5 mode
      } else {
        int lo = (act>0)?5:0;
        selrange(ep2, lo, L, vsel, vw);
      }
      // act1 never reads v, but processed-marking still happens
      fillRole(c,2,vsel,vw,lind,snode,processed,(act!=1)?1:0);
    }

    // edge GEMM descriptors (slots 0..2)
    for(int r2=0;r2<3;r2++){
      ERole er = g_erole[c][r2];
      if(er.enabled && er.op!=4){
        int ac = (er.op==0)?1:((er.op==1)?2:0);
        setGemm(c, r2, 13+r2, 0, er.e, 0, er.e, ac, -1, 10+r2, er.w);
      }
    }

    // node GEMM descriptors (slots 3..5 pre, slot 6 post)
    int cw = c*4;
    if(act==0){
      setGemm(c,3,19,1,cw+0,1,cw+0,0,-1,16,1.f);   // qh = LN(q)@W0+b0
      setGemm(c,4,11,1,cw+1,1,cw+1,0,-1,17,1.f);   // kh = k@W1+b1
      setGemm(c,5,12,1,cw+2,1,cw+2,0,-1,18,1.f);   // vh = v@W2+b2
      setGemm(c,6,20,1,cw+3,1,cw+3,0,10,2+c,aw);   // out = aw*(q + o@W3+b3)
    } else if(act==1){
      setGemm(c,3,10,1,cw+0,1,cw+0,2,-1,16,1.f);   // t0 = gelu(q@W0+b0)
      setGemm(c,4,11,1,cw+1,1,cw+1,0,-1,17,1.f);   // t1 = k@W1+b1
      setGemm(c,6,16,1,cw+3,1,cw+3,0,10,2+c,aw);   // out = aw*(q + (t0*t1)@W3+b3)
      g_gd[c][6].mul=1; g_gd[c][6].srcA[1]=17;
    } else if(act==3){
      setGemm(c,3,10,1,cw+0,-1,0,1,-1,16,1.f);     // t0 = relu(q@W0+k@W1+v@W2)
      g_gd[c][3].nterms=3;
      g_gd[c][3].srcA[1]=11; g_gd[c][3].srcA[2]=12;
      g_gd[c][3].wKind[1]=1; g_gd[c][3].wIdx[1]=cw+1;
      g_gd[c][3].wKind[2]=1; g_gd[c][3].wIdx[2]=cw+2;
      setGemm(c,6,16,1,cw+3,1,cw+3,0,10,2+c,aw);   // out = aw*(q + t0@W3+b3)
    } else if(act==5){
      setGemm(c,3,11,1,cw+1,1,cw+1,2,-1,16,1.f);   // t0 = gelu(k@W1+b1)
    }

    lind += nsrc;
  }
  g_rem_mask = (~processed) & 0xFF;
}

// ---------------- edge prep: LN / copy / identity-scale ----------------
__global__ void prep_kernel(int c, const float* __restrict__ inpute, const float* __restrict__ inputo,
                            const float* __restrict__ edge_g, const float* __restrict__ edge_beta){
  int role = blockIdx.z;
  ERole er = g_erole[c][role];
  if(!er.enabled) return;
  int row = blockIdx.x;
  int t = threadIdx.x;
  const float* x = bufPtrC(er.src, inpute, inputo) + (size_t)row*DIM;
  if(er.op==4){
    float* d = g_qkv[role] + (size_t)row*DIM;
    d[t]     = er.w*x[t];
    d[t+256] = er.w*x[t+256];
    return;
  }
  float* d = g_prep[role] + (size_t)row*DIM;
  float a = x[t], b = x[t+256];
  if(er.op==3){ d[t]=a; d[t+256]=b; return; }
  float s  = blockReduceSum(a+b);
  float mean = s*(1.f/512.f);
  float da=a-mean, db=b-mean;
  float s2 = blockReduceSum(da*da+db*db);
  float rstd = rsqrtf(s2*(1.f/512.f)+1e-6f);
  const float* g  = edge_g    + (size_t)er.e*DIM;
  const float* be = edge_beta + (size_t)er.e*DIM;
  d[t]     = da*rstd*g[t]     + be[t];
  d[t+256] = db*rstd*g[t+256] + be[t+256];
}

// ---------------- LN(q) for MHA ----------------
__global__ void lnq_kernel(int c, const float* __restrict__ node_g, const float* __restrict__ node_beta){
  if(g_node_act[c]!=0) return;
  int row=blockIdx.x, t=threadIdx.x;
  const float* x = g_qkv[0] + (size_t)row*DIM;
  float a=x[t], b=x[t+256];
  float s = blockReduceSum(a+b);
  float mean = s*(1.f/512.f);
  float da=a-mean, db=b-mean;
  float s2 = blockReduceSum(da*da+db*db);
  float rstd = rsqrtf(s2*(1.f/512.f)+1e-6f);
  const float* g  = node_g    + (size_t)c*DIM;
  const float* be = node_beta + (size_t)c*DIM;
  g_lnq[(size_t)row*DIM+t]     = da*rstd*g[t]     + be[t];
  g_lnq[(size_t)row*DIM+t+256] = db*rstd*g[t+256] + be[t+256];
}

// ---------------- generic GEMM: dst = scale*(res + act(sum_t A_t@W_t + b)) ----------------
__global__ void __launch_bounds__(256) gemm_kernel(int c,int slotBase,
  const float* __restrict__ inpute,const float* __restrict__ inputo,
  const float* __restrict__ edge_W,const float* __restrict__ edge_b,
  const float* __restrict__ node_W,const float* __restrict__ node_b)
{
  GemmDesc gd = g_gd[c][slotBase + blockIdx.z];
  if(!gd.enabled) return;
  __shared__ float As[16][128];
  __shared__ float Bs[16][64];
  const int rowBase = blockIdx.y*128;
  const int colBase = blockIdx.x*64;
  const int tid = threadIdx.x;
  const int tx = tid & 15;
  const int ty = tid >> 4;
  float acc[8][4];
  #pragma unroll
  for(int i=0;i<8;i++)
    #pragma unroll
    for(int j=0;j<4;j++) acc[i][j]=0.f;

  const float* A2 = gd.mul ? bufPtrC(gd.srcA[1],inpute,inputo) : nullptr;
  for(int t=0;t<gd.nterms;t++){
    const float* A = bufPtrC(gd.srcA[t],inpute,inputo);
    const float* W = gd.wKind[t] ? (node_W + (size_t)gd.wIdx[t]*262144)
                                 : (edge_W + (size_t)gd.wIdx[t]*262144);
    for(int k0=0;k0<512;k0+=16){
      #pragma unroll
      for(int i=0;i<2;i++){
        int idx = tid*2+i;
        int r = idx>>2, c4 = idx&3;
        float4 av = *(const float4*)(A + (size_t)(rowBase+r)*512 + k0 + c4*4);
        if(A2){
          float4 av2 = *(const float4*)(A2 + (size_t)(rowBase+r)*512 + k0 + c4*4);
          av.x*=av2.x; av.y*=av2.y; av.z*=av2.z; av.w*=av2.w;
        }
        As[c4*4+0][r]=av.x; As[c4*4+1][r]=av.y; As[c4*4+2][r]=av.z; As[c4*4+3][r]=av.w;
      }
      {
        int r = tid>>4, c4 = tid&15;
        float4 wv = *(const float4*)(W + (size_t)(k0+r)*512 + colBase + c4*4);
        Bs[r][c4*4+0]=wv.x; Bs[r][c4*4+1]=wv.y; Bs[r][c4*4+2]=wv.z; Bs[r][c4*4+3]=wv.w;
      }
      __syncthreads();
      #pragma unroll
      for(int k=0;k<16;k++){
        float ra[8], rb[4];
        #pragma unroll
        for(int i=0;i<8;i++) ra[i]=As[k][ty*8+i];
        #pragma unroll
        for(int j=0;j<4;j++) rb[j]=Bs[k][tx*4+j];
        #pragma unroll
        for(int i=0;i<8;i++)
          #pragma unroll
          for(int j=0;j<4;j++) acc[i][j] = fmaf(ra[i],rb[j],acc[i][j]);
      }
      __syncthreads();
    }
  }
  const float* bias = nullptr;
  if(gd.bKind==0)      bias = edge_b + (size_t)gd.bIdx*512;
  else if(gd.bKind==1) bias = node_b + (size_t)gd.bIdx*512;
  const float* res = (gd.resBuf>=0)? bufPtrC(gd.resBuf,inpute,inputo) : nullptr;
  float* dst = bufPtrM(gd.dstBuf);
  #pragma unroll
  for(int i=0;i<8;i++){
    int row = rowBase + ty*8 + i;
    #pragma unroll
    for(int j=0;j<4;j++){
      int col = colBase + tx*4 + j;
      float z = acc[i][j] + (bias? bias[col]:0.f);
      if(gd.actCode==1) z = fmaxf(z,0.f);
      else if(gd.actCode==2) z = geluf(z);
      if(res) z += res[(size_t)row*512+col];
      dst[(size_t)row*512+col] = gd.scale*z;
    }
  }
}

// ---------------- flash attention (B=4,H=8,S=1024,dh=64), masks all-false ----------------
__global__ void __launch_bounds__(256) attn_kernel(int c){
  if(g_node_act[c]!=0) return;
  __shared__ float qs[64][65];
  __shared__ float ks[32][65];
  __shared__ float vs[32][65];
  __shared__ float ps[64][33];
  int tid = threadIdx.x;
  int bh = blockIdx.y; int b = bh>>3, h = bh&7;
  int s0 = blockIdx.x*64;
  const float* Q = g_tt[0]; const float* K = g_tt[1]; const float* V = g_tt[2];
  size_t baseQ = ((size_t)(b*1024 + s0))*DIM + h*64;
  #pragma unroll
  for(int i=0;i<16;i++){
    int e = tid + i*256; int rr = e>>6; int dd = e&63;
    qs[rr][dd] = Q[baseQ + (size_t)rr*DIM + dd];
  }
  int rg = tid>>4, kg = tid&15;
  float acc[4][4]; float m_prev[4], lsum[4];
  #pragma unroll
  for(int i=0;i<4;i++){
    m_prev[i]=-1e30f; lsum[i]=0.f;
    #pragma unroll
    for(int j=0;j<4;j++) acc[i][j]=0.f;
  }
  for(int kt=0;kt<32;kt++){
    __syncthreads();
    size_t baseK = ((size_t)(b*1024 + kt*32))*DIM + h*64;
    #pragma unroll
    for(int i=0;i<8;i++){
      int e = tid + i*256; int rr = e>>6; int dd = e&63;
      ks[rr][dd] = K[baseK + (size_t)rr*DIM + dd];
      vs[rr][dd] = V[baseK + (size_t)rr*DIM + dd];
    }
    __syncthreads();
    float sc[4][2];
    #pragma unroll
    for(int i=0;i<4;i++){ sc[i][0]=0.f; sc[i][1]=0.f; }
    #pragma unroll 4
    for(int d=0;d<64;d++){
      float rk0 = ks[kg*2+0][d], rk1 = ks[kg*2+1][d];
      #pragma unroll
      for(int i=0;i<4;i++){
        float rq = qs[rg*4+i][d];
        sc[i][0] = fmaf(rq,rk0,sc[i][0]);
        sc[i][1] = fmaf(rq,rk1,sc[i][1]);
      }
    }
    #pragma unroll
    for(int i=0;i<4;i++){
      float s0v = sc[i][0]*0.125f, s1v = sc[i][1]*0.125f;
      float mloc = fmaxf(s0v,s1v);
      #pragma unroll
      for(int o=1;o<16;o<<=1) mloc = fmaxf(mloc, __shfl_xor_sync(0xffffffffu,mloc,o));
      float m_new = fmaxf(m_prev[i], mloc);
      float p0 = __expf(s0v-m_new), p1 = __expf(s1v-m_new);
      ps[rg*4+i][kg*2+0]=p0; ps[rg*4+i][kg*2+1]=p1;
      float lloc = p0+p1;
      #pragma unroll
      for(int o=1;o<16;o<<=1) lloc += __shfl_xor_sync(0xffffffffu,lloc,o);
      float corr = __expf(m_prev[i]-m_new);
      lsum[i] = lsum[i]*corr + lloc;
      m_prev[i] = m_new;
      #pragma unroll
      for(int j=0;j<4;j++) acc[i][j]*=corr;
    }
    __syncthreads();
    #pragma unroll 4
    for(int j=0;j<32;j++){
      float v0=vs[j][kg*4+0], v1=vs[j][kg*4+1], v2=vs[j][kg*4+2], v3=vs[j][kg*4+3];
      #pragma unroll
      for(int i=0;i<4;i++){
        float p = ps[rg*4+i][j];
        acc[i][0]=fmaf(p,v0,acc[i][0]); acc[i][1]=fmaf(p,v1,acc[i][1]);
        acc[i][2]=fmaf(p,v2,acc[i][2]); acc[i][3]=fmaf(p,v3,acc[i][3]);
      }
    }
  }
  #pragma unroll
  for(int i=0;i<4;i++){
    float inv = 1.f/lsum[i];
    size_t o = ((size_t)(b*1024 + s0 + rg*4 + i))*DIM + h*64 + kg*4;
    g_attn[o+0]=acc[i][0]*inv; g_attn[o+1]=acc[i][1]*inv;
    g_attn[o+2]=acc[i][2]*inv; g_attn[o+3]=acc[i][3]*inv;
  }
}

// ---------------- elementwise node ops (acts 2,4,5,6,7) ----------------
__global__ void post_elt(int c, const float* __restrict__ node_g, const float* __restrict__ node_beta){
  int act = g_node_act[c];
  if(act==0||act==1||act==3) return;
  float aw = g_node_aw[c];
  int row=blockIdx.x, t=threadIdx.x;
  size_t off=(size_t)row*DIM;
  const float* q=g_qkv[0]+off; const float* k=g_qkv[1]+off; const float* v=g_qkv[2]+off;
  float* o = g_outbuf[c]+off;
  if(act==4){
    o[t]     = aw*(q[t]*sigmoidf(k[t]) + v[t]);
    o[t+256] = aw*(q[t+256]*sigmoidf(k[t+256]) + v[t+256]);
    return;
  }
  if(act==5){
    const float* tt = g_tt[0]+off;
    o[t]=aw*(q[t]+tt[t]); o[t+256]=aw*(q[t+256]+tt[t+256]);
    return;
  }
  if(act==6){
    o[t]=aw*(q[t]+k[t]); o[t+256]=aw*(q[t+256]+k[t+256]);
    return;
  }
  // act 2: LN(q+k+v), act 7: LN(q)
  float a,b;
  if(act==2){ a=q[t]+k[t]+v[t]; b=q[t+256]+k[t+256]+v[t+256]; }
  else      { a=q[t];           b=q[t+256]; }
  float s = blockReduceSum(a+b);
  float mean = s*(1.f/512.f);
  float da=a-mean, db=b-mean;
  float s2 = blockReduceSum(da*da+db*db);
  float rstd = rsqrtf(s2*(1.f/512.f)+1e-6f);
  const float* g  = node_g    + (size_t)c*DIM;
  const float* be = node_beta + (size_t)c*DIM;
  o[t]     = aw*(da*rstd*g[t]     + be[t]);
  o[t+256] = aw*(db*rstd*g[t+256] + be[t+256]);
}

// ---------------- final: sum remaining nodes + LN ----------------
__global__ void final_kernel(const float* __restrict__ og, const float* __restrict__ obe, float* __restrict__ out){
  int row=blockIdx.x, t=threadIdx.x;
  int mask = g_rem_mask;
  size_t off=(size_t)row*DIM;
  float a=0.f, b=0.f;
  #pragma unroll
  for(int i=0;i<8;i++) if((mask>>i)&1){
    a += g_outbuf[i][off+t];
    b += g_outbuf[i][off+t+256];
  }
  float s = blockReduceSum(a+b);
  float mean = s*(1.f/512.f);
  float da=a-mean, db=b-mean;
  float s2 = blockReduceSum(da*da+db*db);
  float rstd = rsqrtf(s2*(1.f/512.f)+1e-6f);
  out[off+t]     = da*rstd*og[t]     + obe[t];
  out[off+t+256] = db*rstd*og[t+256] + obe[t+256];
}

extern "C" void kernel_launch(void* const* d_in, const int* in_sizes, int n_in,
                              void* d_out, int out_size) {
  (void)in_sizes; (void)n_in; (void)out_size;
  const float* inpute    = (const float*)d_in[0];
  const float* inputo    = (const float*)d_in[1];
  const float* node_p    = (const float*)d_in[2];
  const float* edge_p    = (const float*)d_in[3];
  const float* edge_W    = (const float*)d_in[4];
  const float* edge_b    = (const float*)d_in[5];
  const float* edge_g    = (const float*)d_in[6];
  const float* edge_beta = (const float*)d_in[7];
  const float* node_W    = (const float*)d_in[8];
  const float* node_b    = (const float*)d_in[9];
  const float* node_g    = (const float*)d_in[10];
  const float* node_beta = (const float*)d_in[11];
  const float* out_g     = (const float*)d_in[12];
  const float* out_beta  = (const float*)d_in[13];
  float* out = (float*)d_out;

  route_kernel<<<1,1>>>(node_p, edge_p);
  for(int c=0;c<8;c++){
    prep_kernel<<<dim3(NROWS,1,3),256>>>(c, inpute, inputo, edge_g, edge_beta);
    gemm_kernel<<<dim3(8,32,3),256>>>(c,0,inpute,inputo,edge_W,edge_b,node_W,node_b);
    lnq_kernel<<<NROWS,256>>>(c, node_g, node_beta);
    gemm_kernel<<<dim3(8,32,3),256>>>(c,3,inpute,inputo,edge_W,edge_b,node_W,node_b);
    attn_kernel<<<dim3(16,32),256>>>(c);
    gemm_kernel<<<dim3(8,32,1),256>>>(c,6,inpute,inputo,edge_W,edge_b,node_W,node_b);
    post_elt<<<NROWS,256>>>(c, node_g, node_beta);
  }
  final_kernel<<<NROWS,256>>>(out_g, out_beta, out);
}

// round 3
// speedup vs baseline: 1.4782x; 1.4782x over previous
#include <cuda_runtime.h>
#include <math.h>

#define NROWS 4096
#define DIM 512

// ---------------- descriptors ----------------
struct ERole { int enabled; int src; int e; int op; float w; };
struct GemmDesc {
  int enabled, nterms, mul;
  int srcA[3];
  int wKind[3], wIdx[3];
  int bKind, bIdx;
  int actCode;          // 0 none, 1 relu, 2 gelu
  int resBuf, dstBuf;
  float scale;
};

__device__ ERole    g_erole[8][3];
__device__ GemmDesc g_gd[8][7];
__device__ int      g_node_act[8];
__device__ float    g_node_aw[8];
__device__ int      g_rem_mask;

// ---------------- big scratch buffers (device .bss) ----------------
__device__ float g_outbuf[8][NROWS*DIM]; // node outputs
__device__ float g_qkv[3][NROWS*DIM];    // q,k,v edge outputs
__device__ float g_prep[3][NROWS*DIM];   // normalized/copied edge inputs
__device__ float g_tt[3][NROWS*DIM];     // node projection temporaries
__device__ float g_lnq[NROWS*DIM];       // LN(q) for MHA
__device__ float g_attn[NROWS*DIM];      // attention output

// buffer id map: 0 inpute, 1 inputo, 2..9 g_outbuf[0..7], 10..12 g_qkv,
// 13..15 g_prep, 16..18 g_tt, 19 g_lnq, 20 g_attn
__device__ __forceinline__ const float* bufPtrC(int id, const float* inpute, const float* inputo){
  if(id==0) return inpute;
  if(id==1) return inputo;
  if(id<10) return g_outbuf[id-2];
  if(id<13) return g_qkv[id-10];
  if(id<16) return g_prep[id-13];
  if(id<19) return g_tt[id-16];
  if(id==19) return g_lnq;
  return g_attn;
}
__device__ __forceinline__ float* bufPtrM(int id){
  if(id<10) return g_outbuf[id-2];
  if(id<13) return g_qkv[id-10];
  if(id<16) return g_prep[id-13];
  if(id<19) return g_tt[id-16];
  if(id==19) return g_lnq;
  return g_attn;
}

__device__ __forceinline__ float geluf(float x){
  float inner = 0.7978845608028654f*(x + 0.044715f*x*x*x);
  return 0.5f*x*(1.f+tanhf(inner));
}
__device__ __forceinline__ float sigmoidf(float x){ return 1.f/(1.f+expf(-x)); }

__device__ __forceinline__ float blockReduceSum(float v){
  __shared__ float red[32];
  int lane = threadIdx.x & 31, w = threadIdx.x >> 5;
  #pragma unroll
  for(int o=16;o;o>>=1) v += __shfl_xor_sync(0xffffffffu, v, o);
  if(lane==0) red[w]=v;
  __syncthreads();
  if(w==0){
    float x = (lane < (int)(blockDim.x>>5)) ? red[lane] : 0.f;
    #pragma unroll
    for(int o=16;o;o>>=1) x += __shfl_xor_sync(0xffffffffu, x, o);
    if(lane==0) red[0]=x;
  }
  __syncthreads();
  float r = red[0];
  __syncthreads();
  return r;
}

// ---------------- routing ----------------
__device__ void selrange(const float* p, int lo, int hi, int& sel, float& w){
  int bi=lo; float bv=p[lo];
  for(int i=lo+1;i<hi;i++) if(p[i]>bv){bv=p[i];bi=i;}
  float s=0.f;
  for(int i=lo;i<hi;i++) s += expf(p[i]-bv);
  sel=bi; w=1.f/s;  // exp(p[bi]-max)==1
}

__device__ void fillRole(int c,int role,int sel,float w,int lind,int snode,int& processed,int computeEnabled){
  int se = sel/5, op = sel%5;
  int inn = (se==0)? -2 : snode+se;
  if(inn>=0) processed |= (1<<inn);
  int src = (inn==-2)?0 : ((inn==-1)?1 : (2+inn));
  ERole er; er.enabled=computeEnabled; er.src=src; er.e=lind+se; er.op=op; er.w=w;
  g_erole[c][role]=er;
}

__device__ void setGemm(int c,int slot,int src0,int wKind0,int wIdx0,int bKind,int bIdx,
                        int actCode,int resBuf,int dstBuf,float scale){
  GemmDesc gd;
  gd.enabled=1; gd.nterms=1; gd.mul=0;
  gd.srcA[0]=src0; gd.srcA[1]=0; gd.srcA[2]=0;
  gd.wKind[0]=wKind0; gd.wIdx[0]=wIdx0;
  gd.wKind[1]=0; gd.wIdx[1]=0; gd.wKind[2]=0; gd.wIdx[2]=0;
  gd.bKind=bKind; gd.bIdx=bIdx;
  gd.actCode=actCode; gd.resBuf=resBuf; gd.dstBuf=dstBuf; gd.scale=scale;
  g_gd[c][slot]=gd;
}

__global__ void route_kernel(const float* __restrict__ node_p, const float* __restrict__ edge_p){
  if(threadIdx.x!=0 || blockIdx.x!=0) return;
  int processed = 0;
  int lind = 0;
  for(int c=0;c<8;c++){
    for(int s=0;s<7;s++) g_gd[c][s].enabled=0;
    for(int r=0;r<3;r++) g_erole[c][r].enabled=0;

    int nsrc = (c+2<5)? c+2 : 5;
    int snode = c - nsrc;
    int L = nsrc*5;
    const float* ep0 = edge_p + lind*5;
    const float* ep1 = edge_p + 170 + lind*5;
    const float* ep2 = edge_p + 340 + lind*5;
    const float* np  = node_p + c*8;

    int act=0; { float b=np[0]; for(int i=1;i<8;i++) if(np[i]>b){b=np[i];act=i;} }
    float aw;
    { float m=np[0]; for(int i=1;i<8;i++) m=fmaxf(m,np[i]);
      float s=0.f; for(int i=0;i<8;i++) s+=expf(np[i]-m);
      aw = expf(np[act]-m)/s; }
    g_node_act[c]=act; g_node_aw[c]=aw;

    // q: mask first 5 (encoder source masked for q)
    int qsel; float qw;
    selrange(ep0, 5, L, qsel, qw);
    fillRole(c,0,qsel,qw,lind,snode,processed,1);

    // k (act<7): mask first 5 iff act>0
    int ksel = -1;
    if(act<7){
      int lo = (act>0)?5:0;
      float kw;
      selrange(ep1, lo, L, ksel, kw);
      fillRole(c,1,ksel,kw,lind,snode,processed,1);
    }
    // v (act<5)
    if(act<5){
      int vsel; float vw;
      if(act==0 && (ksel/5)==0){
        selrange(ep2, 0, 5, vsel, vw);           // first5 mode
      } else {
        int lo = (act>0)?5:0;
        selrange(ep2, lo, L, vsel, vw);
      }
      // act1 never reads v, but processed-marking still happens
      fillRole(c,2,vsel,vw,lind,snode,processed,(act!=1)?1:0);
    }

    // edge GEMM descriptors (slots 0..2)
    for(int r2=0;r2<3;r2++){
      ERole er = g_erole[c][r2];
      if(er.enabled && er.op!=4){
        int ac = (er.op==0)?1:((er.op==1)?2:0);
        setGemm(c, r2, 13+r2, 0, er.e, 0, er.e, ac, -1, 10+r2, er.w);
      }
    }

    // node GEMM descriptors (slots 3..5 pre, slot 6 post)
    int cw = c*4;
    if(act==0){
      setGemm(c,3,19,1,cw+0,1,cw+0,0,-1,16,1.f);   // qh = LN(q)@W0+b0
      setGemm(c,4,11,1,cw+1,1,cw+1,0,-1,17,1.f);   // kh = k@W1+b1
      setGemm(c,5,12,1,cw+2,1,cw+2,0,-1,18,1.f);   // vh = v@W2+b2
      setGemm(c,6,20,1,cw+3,1,cw+3,0,10,2+c,aw);   // out = aw*(q + o@W3+b3)
    } else if(act==1){
      setGemm(c,3,10,1,cw+0,1,cw+0,2,-1,16,1.f);   // t0 = gelu(q@W0+b0)
      setGemm(c,4,11,1,cw+1,1,cw+1,0,-1,17,1.f);   // t1 = k@W1+b1
      setGemm(c,6,16,1,cw+3,1,cw+3,0,10,2+c,aw);   // out = aw*(q + (t0*t1)@W3+b3)
      g_gd[c][6].mul=1; g_gd[c][6].srcA[1]=17;
    } else if(act==3){
      setGemm(c,3,10,1,cw+0,-1,0,1,-1,16,1.f);     // t0 = relu(q@W0+k@W1+v@W2)
      g_gd[c][3].nterms=3;
      g_gd[c][3].srcA[1]=11; g_gd[c][3].srcA[2]=12;
      g_gd[c][3].wKind[1]=1; g_gd[c][3].wIdx[1]=cw+1;
      g_gd[c][3].wKind[2]=1; g_gd[c][3].wIdx[2]=cw+2;
      setGemm(c,6,16,1,cw+3,1,cw+3,0,10,2+c,aw);   // out = aw*(q + t0@W3+b3)
    } else if(act==5){
      setGemm(c,3,11,1,cw+1,1,cw+1,2,-1,16,1.f);   // t0 = gelu(k@W1+b1)
    }

    lind += nsrc;
  }
  g_rem_mask = (~processed) & 0xFF;
}

// ---------------- edge prep: LN / copy / identity-scale ----------------
__global__ void prep_kernel(int c, const float* __restrict__ inpute, const float* __restrict__ inputo,
                            const float* __restrict__ edge_g, const float* __restrict__ edge_beta){
  int role = blockIdx.z;
  ERole er = g_erole[c][role];
  if(!er.enabled) return;
  int row = blockIdx.x;
  int t = threadIdx.x;
  const float* x = bufPtrC(er.src, inpute, inputo) + (size_t)row*DIM;
  if(er.op==4){
    float* d = g_qkv[role] + (size_t)row*DIM;
    d[t]     = er.w*x[t];
    d[t+256] = er.w*x[t+256];
    return;
  }
  float* d = g_prep[role] + (size_t)row*DIM;
  float a = x[t], b = x[t+256];
  if(er.op==3){ d[t]=a; d[t+256]=b; return; }
  float s  = blockReduceSum(a+b);
  float mean = s*(1.f/512.f);
  float da=a-mean, db=b-mean;
  float s2 = blockReduceSum(da*da+db*db);
  float rstd = rsqrtf(s2*(1.f/512.f)+1e-6f);
  const float* g  = edge_g    + (size_t)er.e*DIM;
  const float* be = edge_beta + (size_t)er.e*DIM;
  d[t]     = da*rstd*g[t]     + be[t];
  d[t+256] = db*rstd*g[t+256] + be[t+256];
}

// ---------------- LN(q) for MHA ----------------
__global__ void lnq_kernel(int c, const float* __restrict__ node_g, const float* __restrict__ node_beta){
  if(g_node_act[c]!=0) return;
  int row=blockIdx.x, t=threadIdx.x;
  const float* x = g_qkv[0] + (size_t)row*DIM;
  float a=x[t], b=x[t+256];
  float s = blockReduceSum(a+b);
  float mean = s*(1.f/512.f);
  float da=a-mean, db=b-mean;
  float s2 = blockReduceSum(da*da+db*db);
  float rstd = rsqrtf(s2*(1.f/512.f)+1e-6f);
  const float* g  = node_g    + (size_t)c*DIM;
  const float* be = node_beta + (size_t)c*DIM;
  g_lnq[(size_t)row*DIM+t]     = da*rstd*g[t]     + be[t];
  g_lnq[(size_t)row*DIM+t+256] = db*rstd*g[t+256] + be[t+256];
}

// ---------------- generic GEMM: dst = scale*(res + act(sum_t A_t@W_t + b)) ----------------
// 128x128 tile, 256 threads, 8x8 per thread, k-step 8, double-buffered smem.
#define APAD 132
__global__ void __launch_bounds__(256,2) gemm_kernel(int c,int slotBase,
  const float* __restrict__ inpute,const float* __restrict__ inputo,
  const float* __restrict__ edge_W,const float* __restrict__ edge_b,
  const float* __restrict__ node_W,const float* __restrict__ node_b)
{
  GemmDesc gd = g_gd[c][slotBase + blockIdx.z];
  if(!gd.enabled) return;
  __shared__ float As[2][8][APAD];
  __shared__ float Bs[2][8][APAD];
  const int rowBase = blockIdx.y*128;
  const int colBase = blockIdx.x*128;
  const int tid = threadIdx.x;
  const int tx = tid & 15;       // 16 col-groups of 8
  const int ty = tid >> 4;       // 16 row-groups of 8
  // global loader coords
  const int ar = tid >> 1;            // 0..127 rows of A tile
  const int ac = (tid & 1) * 4;       // 0 or 4 within k-step
  const int br = tid >> 5;            // 0..7 k-rows of B tile
  const int bc = (tid & 31) * 4;      // 0..124 cols

  float acc[8][8];
  #pragma unroll
  for(int i=0;i<8;i++)
    #pragma unroll
    for(int j=0;j<8;j++) acc[i][j]=0.f;

  const float* A2base = gd.mul ? bufPtrC(gd.srcA[1],inpute,inputo) : nullptr;

  for(int t=0;t<gd.nterms;t++){
    const float* A = bufPtrC(gd.srcA[t],inpute,inputo);
    const float* W = gd.wKind[t] ? (node_W + (size_t)gd.wIdx[t]*262144)
                                 : (edge_W + (size_t)gd.wIdx[t]*262144);
    const float* Aptr  = A + (size_t)(rowBase+ar)*512 + ac;
    const float* A2ptr = A2base ? A2base + (size_t)(rowBase+ar)*512 + ac : nullptr;
    const float* Wptr  = W + (size_t)br*512 + colBase + bc;

    // prologue: tile k0=0 into buf 0
    float4 av = *(const float4*)(Aptr);
    if(A2ptr){ float4 u = *(const float4*)(A2ptr); av.x*=u.x; av.y*=u.y; av.z*=u.z; av.w*=u.w; }
    float4 bv = *(const float4*)(Wptr);
    As[0][ac+0][ar]=av.x; As[0][ac+1][ar]=av.y; As[0][ac+2][ar]=av.z; As[0][ac+3][ar]=av.w;
    *(float4*)&Bs[0][br][bc] = bv;
    __syncthreads();

    int buf=0;
    for(int k0=8;k0<512;k0+=8){
      // prefetch next tile
      float4 an = *(const float4*)(Aptr + k0);
      if(A2ptr){ float4 u = *(const float4*)(A2ptr + k0); an.x*=u.x; an.y*=u.y; an.z*=u.z; an.w*=u.w; }
      float4 bn = *(const float4*)(Wptr + (size_t)k0*512);
      // compute current buf
      {
        const float (*Ab)[APAD] = As[buf];
        const float (*Bb)[APAD] = Bs[buf];
        #pragma unroll
        for(int k=0;k<8;k++){
          float4 a0 = *(const float4*)&Ab[k][ty*8];
          float4 a1 = *(const float4*)&Ab[k][ty*8+4];
          float4 b0 = *(const float4*)&Bb[k][tx*8];
          float4 b1 = *(const float4*)&Bb[k][tx*8+4];
          float ra[8]={a0.x,a0.y,a0.z,a0.w,a1.x,a1.y,a1.z,a1.w};
          float rb[8]={b0.x,b0.y,b0.z,b0.w,b1.x,b1.y,b1.z,b1.w};
          #pragma unroll
          for(int i=0;i<8;i++)
            #pragma unroll
            for(int j=0;j<8;j++) acc[i][j]=fmaf(ra[i],rb[j],acc[i][j]);
        }
      }
      // store next into other buf
      int nb = buf^1;
      As[nb][ac+0][ar]=an.x; As[nb][ac+1][ar]=an.y; As[nb][ac+2][ar]=an.z; As[nb][ac+3][ar]=an.w;
      *(float4*)&Bs[nb][br][bc] = bn;
      __syncthreads();
      buf = nb;
    }
    // last tile
    {
      const float (*Ab)[APAD] = As[buf];
      const float (*Bb)[APAD] = Bs[buf];
      #pragma unroll
      for(int k=0;k<8;k++){
        float4 a0 = *(const float4*)&Ab[k][ty*8];
        float4 a1 = *(const float4*)&Ab[k][ty*8+4];
        float4 b0 = *(const float4*)&Bb[k][tx*8];
        float4 b1 = *(const float4*)&Bb[k][tx*8+4];
        float ra[8]={a0.x,a0.y,a0.z,a0.w,a1.x,a1.y,a1.z,a1.w};
        float rb[8]={b0.x,b0.y,b0.z,b0.w,b1.x,b1.y,b1.z,b1.w};
        #pragma unroll
        for(int i=0;i<8;i++)
          #pragma unroll
          for(int j=0;j<8;j++) acc[i][j]=fmaf(ra[i],rb[j],acc[i][j]);
      }
    }
    if(t+1<gd.nterms) __syncthreads();
  }

  const float* bias = nullptr;
  if(gd.bKind==0)      bias = edge_b + (size_t)gd.bIdx*512;
  else if(gd.bKind==1) bias = node_b + (size_t)gd.bIdx*512;
  const float* res = (gd.resBuf>=0)? bufPtrC(gd.resBuf,inpute,inputo) : nullptr;
  float* dst = bufPtrM(gd.dstBuf);
  #pragma unroll
  for(int i=0;i<8;i++){
    int row = rowBase + ty*8 + i;
    #pragma unroll
    for(int j=0;j<8;j++){
      int col = colBase + tx*8 + j;
      float z = acc[i][j] + (bias? bias[col]:0.f);
      if(gd.actCode==1) z = fmaxf(z,0.f);
      else if(gd.actCode==2) z = geluf(z);
      if(res) z += res[(size_t)row*512+col];
      dst[(size_t)row*512+col] = gd.scale*z;
    }
  }
}

// ---------------- flash attention (B=4,H=8,S=1024,dh=64), masks all-false ----------------
__global__ void __launch_bounds__(256) attn_kernel(int c){
  if(g_node_act[c]!=0) return;
  __shared__ float qs[64][65];
  __shared__ float ks[32][65];
  __shared__ float vs[32][65];
  __shared__ float ps[64][33];
  int tid = threadIdx.x;
  int bh = blockIdx.y; int b = bh>>3, h = bh&7;
  int s0 = blockIdx.x*64;
  const float* Q = g_tt[0]; const float* K = g_tt[1]; const float* V = g_tt[2];
  size_t baseQ = ((size_t)(b*1024 + s0))*DIM + h*64;
  #pragma unroll
  for(int i=0;i<16;i++){
    int e = tid + i*256; int rr = e>>6; int dd = e&63;
    qs[rr][dd] = Q[baseQ + (size_t)rr*DIM + dd];
  }
  int rg = tid>>4, kg = tid&15;
  float acc[4][4]; float m_prev[4], lsum[4];
  #pragma unroll
  for(int i=0;i<4;i++){
    m_prev[i]=-1e30f; lsum[i]=0.f;
    #pragma unroll
    for(int j=0;j<4;j++) acc[i][j]=0.f;
  }
  for(int kt=0;kt<32;kt++){
    __syncthreads();
    size_t baseK = ((size_t)(b*1024 + kt*32))*DIM + h*64;
    #pragma unroll
    for(int i=0;i<8;i++){
      int e = tid + i*256; int rr = e>>6; int dd = e&63;
      ks[rr][dd] = K[baseK + (size_t)rr*DIM + dd];
      vs[rr][dd] = V[baseK + (size_t)rr*DIM + dd];
    }
    __syncthreads();
    float sc[4][2];
    #pragma unroll
    for(int i=0;i<4;i++){ sc[i][0]=0.f; sc[i][1]=0.f; }
    #pragma unroll 4
    for(int d=0;d<64;d++){
      float rk0 = ks[kg*2+0][d], rk1 = ks[kg*2+1][d];
      #pragma unroll
      for(int i=0;i<4;i++){
        float rq = qs[rg*4+i][d];
        sc[i][0] = fmaf(rq,rk0,sc[i][0]);
        sc[i][1] = fmaf(rq,rk1,sc[i][1]);
      }
    }
    #pragma unroll
    for(int i=0;i<4;i++){
      float s0v = sc[i][0]*0.125f, s1v = sc[i][1]*0.125f;
      float mloc = fmaxf(s0v,s1v);
      #pragma unroll
      for(int o=1;o<16;o<<=1) mloc = fmaxf(mloc, __shfl_xor_sync(0xffffffffu,mloc,o));
      float m_new = fmaxf(m_prev[i], mloc);
      float p0 = __expf(s0v-m_new), p1 = __expf(s1v-m_new);
      ps[rg*4+i][kg*2+0]=p0; ps[rg*4+i][kg*2+1]=p1;
      float lloc = p0+p1;
      #pragma unroll
      for(int o=1;o<16;o<<=1) lloc += __shfl_xor_sync(0xffffffffu,lloc,o);
      float corr = __expf(m_prev[i]-m_new);
      lsum[i] = lsum[i]*corr + lloc;
      m_prev[i] = m_new;
      #pragma unroll
      for(int j=0;j<4;j++) acc[i][j]*=corr;
    }
    __syncthreads();
    #pragma unroll 4
    for(int j=0;j<32;j++){
      float v0=vs[j][kg*4+0], v1=vs[j][kg*4+1], v2=vs[j][kg*4+2], v3=vs[j][kg*4+3];
      #pragma unroll
      for(int i=0;i<4;i++){
        float p = ps[rg*4+i][j];
        acc[i][0]=fmaf(p,v0,acc[i][0]); acc[i][1]=fmaf(p,v1,acc[i][1]);
        acc[i][2]=fmaf(p,v2,acc[i][2]); acc[i][3]=fmaf(p,v3,acc[i][3]);
      }
    }
  }
  #pragma unroll
  for(int i=0;i<4;i++){
    float inv = 1.f/lsum[i];
    size_t o = ((size_t)(b*1024 + s0 + rg*4 + i))*DIM + h*64 + kg*4;
    g_attn[o+0]=acc[i][0]*inv; g_attn[o+1]=acc[i][1]*inv;
    g_attn[o+2]=acc[i][2]*inv; g_attn[o+3]=acc[i][3]*inv;
  }
}

// ---------------- elementwise node ops (acts 2,4,5,6,7) ----------------
__global__ void post_elt(int c, const float* __restrict__ node_g, const float* __restrict__ node_beta){
  int act = g_node_act[c];
  if(act==0||act==1||act==3) return;
  float aw = g_node_aw[c];
  int row=blockIdx.x, t=threadIdx.x;
  size_t off=(size_t)row*DIM;
  const float* q=g_qkv[0]+off; const float* k=g_qkv[1]+off; const float* v=g_qkv[2]+off;
  float* o = g_outbuf[c]+off;
  if(act==4){
    o[t]     = aw*(q[t]*sigmoidf(k[t]) + v[t]);
    o[t+256] = aw*(q[t+256]*sigmoidf(k[t+256]) + v[t+256]);
    return;
  }
  if(act==5){
    const float* tt = g_tt[0]+off;
    o[t]=aw*(q[t]+tt[t]); o[t+256]=aw*(q[t+256]+tt[t+256]);
    return;
  }
  if(act==6){
    o[t]=aw*(q[t]+k[t]); o[t+256]=aw*(q[t+256]+k[t+256]);
    return;
  }
  // act 2: LN(q+k+v), act 7: LN(q)
  float a,b;
  if(act==2){ a=q[t]+k[t]+v[t]; b=q[t+256]+k[t+256]+v[t+256]; }
  else      { a=q[t];           b=q[t+256]; }
  float s = blockReduceSum(a+b);
  float mean = s*(1.f/512.f);
  float da=a-mean, db=b-mean;
  float s2 = blockReduceSum(da*da+db*db);
  float rstd = rsqrtf(s2*(1.f/512.f)+1e-6f);
  const float* g  = node_g    + (size_t)c*DIM;
  const float* be = node_beta + (size_t)c*DIM;
  o[t]     = aw*(da*rstd*g[t]     + be[t]);
  o[t+256] = aw*(db*rstd*g[t+256] + be[t+256]);
}

// ---------------- final: sum remaining nodes + LN ----------------
__global__ void final_kernel(const float* __restrict__ og, const float* __restrict__ obe, float* __restrict__ out){
  int row=blockIdx.x, t=threadIdx.x;
  int mask = g_rem_mask;
  size_t off=(size_t)row*DIM;
  float a=0.f, b=0.f;
  #pragma unroll
  for(int i=0;i<8;i++) if((mask>>i)&1){
    a += g_outbuf[i][off+t];
    b += g_outbuf[i][off+t+256];
  }
  float s = blockReduceSum(a+b);
  float mean = s*(1.f/512.f);
  float da=a-mean, db=b-mean;
  float s2 = blockReduceSum(da*da+db*db);
  float rstd = rsqrtf(s2*(1.f/512.f)+1e-6f);
  out[off+t]     = da*rstd*og[t]     + obe[t];
  out[off+t+256] = db*rstd*og[t+256] + obe[t+256];
}

extern "C" void kernel_launch(void* const* d_in, const int* in_sizes, int n_in,
                              void* d_out, int out_size) {
  (void)in_sizes; (void)n_in; (void)out_size;
  const float* inpute    = (const float*)d_in[0];
  const float* inputo    = (const float*)d_in[1];
  const float* node_p    = (const float*)d_in[2];
  const float* edge_p    = (const float*)d_in[3];
  const float* edge_W    = (const float*)d_in[4];
  const float* edge_b    = (const float*)d_in[5];
  const float* edge_g    = (const float*)d_in[6];
  const float* edge_beta = (const float*)d_in[7];
  const float* node_W    = (const float*)d_in[8];
  const float* node_b    = (const float*)d_in[9];
  const float* node_g    = (const float*)d_in[10];
  const float* node_beta = (const float*)d_in[11];
  const float* out_g     = (const float*)d_in[12];
  const float* out_beta  = (const float*)d_in[13];
  float* out = (float*)d_out;

  route_kernel<<<1,1>>>(node_p, edge_p);
  for(int c=0;c<8;c++){
    prep_kernel<<<dim3(NROWS,1,3),256>>>(c, inpute, inputo, edge_g, edge_beta);
    gemm_kernel<<<dim3(4,32,3),256>>>(c,0,inpute,inputo,edge_W,edge_b,node_W,node_b);
    lnq_kernel<<<NROWS,256>>>(c, node_g, node_beta);
    gemm_kernel<<<dim3(4,32,3),256>>>(c,3,inpute,inputo,edge_W,edge_b,node_W,node_b);
    attn_kernel<<<dim3(16,32),256>>>(c);
    gemm_kernel<<<dim3(4,32,1),256>>>(c,6,inpute,inputo,edge_W,edge_b,node_W,node_b);
    post_elt<<<NROWS,256>>>(c, node_g, node_beta);
  }
  final_kernel<<<NROWS,256>>>(out_g, out_beta, out);
}

// round 5
// speedup vs baseline: 3.2718x; 2.2134x over previous
#include <cuda_runtime.h>
#include <cuda_bf16.h>
#include <math.h>
#include <stdint.h>

#define NROWS 4096
#define DIM 512

// ---------------- descriptors ----------------
struct ERole { int enabled; int src; int e; int op; float w; };
struct GemmDesc {
  int enabled, nterms, mul;
  int srcA[3];
  int wKind[3], wIdx[3];
  int bKind, bIdx;
  int actCode;          // 0 none, 1 relu, 2 gelu
  int resBuf, dstBuf;
  float scale;
};

__device__ ERole    g_erole[8][3];
__device__ GemmDesc g_gd[8][7];
__device__ int      g_node_act[8];
__device__ float    g_node_aw[8];
__device__ int      g_rem_mask;

// ---------------- big scratch buffers (device .bss) ----------------
__device__ float g_outbuf[8][NROWS*DIM];
__device__ float g_qkv[3][NROWS*DIM];
__device__ float g_prep[3][NROWS*DIM];
__device__ float g_tt[3][NROWS*DIM];
__device__ float g_lnq[NROWS*DIM];
__device__ float g_attn[NROWS*DIM];

// transposed bf16 weights: [w][n*512+k], hi and lo parts. w: 0..33 edge, 34..65 node
__device__ __nv_bfloat16 g_Wth[66u*262144u];
__device__ __nv_bfloat16 g_Wtl[66u*262144u];

// buffer id map: 0 inpute, 1 inputo, 2..9 g_outbuf[0..7], 10..12 g_qkv,
// 13..15 g_prep, 16..18 g_tt, 19 g_lnq, 20 g_attn
__device__ __forceinline__ const float* bufPtrC(int id, const float* inpute, const float* inputo){
  if(id==0) return inpute;
  if(id==1) return inputo;
  if(id<10) return g_outbuf[id-2];
  if(id<13) return g_qkv[id-10];
  if(id<16) return g_prep[id-13];
  if(id<19) return g_tt[id-16];
  if(id==19) return g_lnq;
  return g_attn;
}
__device__ __forceinline__ float* bufPtrM(int id){
  if(id<10) return g_outbuf[id-2];
  if(id<13) return g_qkv[id-10];
  if(id<16) return g_prep[id-13];
  if(id<19) return g_tt[id-16];
  if(id==19) return g_lnq;
  return g_attn;
}

__device__ __forceinline__ float geluf(float x){
  float inner = 0.7978845608028654f*(x + 0.044715f*x*x*x);
  return 0.5f*x*(1.f+tanhf(inner));
}
__device__ __forceinline__ float sigmoidf(float x){ return 1.f/(1.f+expf(-x)); }

__device__ __forceinline__ float blockReduceSum(float v){
  __shared__ float red[32];
  int lane = threadIdx.x & 31, w = threadIdx.x >> 5;
  #pragma unroll
  for(int o=16;o;o>>=1) v += __shfl_xor_sync(0xffffffffu, v, o);
  if(lane==0) red[w]=v;
  __syncthreads();
  if(w==0){
    float x = (lane < (int)(blockDim.x>>5)) ? red[lane] : 0.f;
    #pragma unroll
    for(int o=16;o;o>>=1) x += __shfl_xor_sync(0xffffffffu, x, o);
    if(lane==0) red[0]=x;
  }
  __syncthreads();
  float r = red[0];
  __syncthreads();
  return r;
}

// ---------------- routing ----------------
__device__ void selrange(const float* p, int lo, int hi, int& sel, float& w){
  int bi=lo; float bv=p[lo];
  for(int i=lo+1;i<hi;i++) if(p[i]>bv){bv=p[i];bi=i;}
  float s=0.f;
  for(int i=lo;i<hi;i++) s += expf(p[i]-bv);
  sel=bi; w=1.f/s;
}

__device__ void fillRole(int c,int role,int sel,float w,int lind,int snode,int& processed,int computeEnabled){
  int se = sel/5, op = sel%5;
  int inn = (se==0)? -2 : snode+se;
  if(inn>=0) processed |= (1<<inn);
  int src = (inn==-2)?0 : ((inn==-1)?1 : (2+inn));
  ERole er; er.enabled=computeEnabled; er.src=src; er.e=lind+se; er.op=op; er.w=w;
  g_erole[c][role]=er;
}

__device__ void setGemm(int c,int slot,int src0,int wKind0,int wIdx0,int bKind,int bIdx,
                        int actCode,int resBuf,int dstBuf,float scale){
  GemmDesc gd;
  gd.enabled=1; gd.nterms=1; gd.mul=0;
  gd.srcA[0]=src0; gd.srcA[1]=0; gd.srcA[2]=0;
  gd.wKind[0]=wKind0; gd.wIdx[0]=wIdx0;
  gd.wKind[1]=0; gd.wIdx[1]=0; gd.wKind[2]=0; gd.wIdx[2]=0;
  gd.bKind=bKind; gd.bIdx=bIdx;
  gd.actCode=actCode; gd.resBuf=resBuf; gd.dstBuf=dstBuf; gd.scale=scale;
  g_gd[c][slot]=gd;
}

__global__ void route_kernel(const float* __restrict__ node_p, const float* __restrict__ edge_p){
  if(threadIdx.x!=0 || blockIdx.x!=0) return;
  int processed = 0;
  int lind = 0;
  for(int c=0;c<8;c++){
    for(int s=0;s<7;s++) g_gd[c][s].enabled=0;
    for(int r=0;r<3;r++) g_erole[c][r].enabled=0;

    int nsrc = (c+2<5)? c+2 : 5;
    int snode = c - nsrc;
    int L = nsrc*5;
    const float* ep0 = edge_p + lind*5;
    const float* ep1 = edge_p + 170 + lind*5;
    const float* ep2 = edge_p + 340 + lind*5;
    const float* np  = node_p + c*8;

    int act=0; { float b=np[0]; for(int i=1;i<8;i++) if(np[i]>b){b=np[i];act=i;} }
    float aw;
    { float m=np[0]; for(int i=1;i<8;i++) m=fmaxf(m,np[i]);
      float s=0.f; for(int i=0;i<8;i++) s+=expf(np[i]-m);
      aw = expf(np[act]-m)/s; }
    g_node_act[c]=act; g_node_aw[c]=aw;

    int qsel; float qw;
    selrange(ep0, 5, L, qsel, qw);
    fillRole(c,0,qsel,qw,lind,snode,processed,1);

    int ksel = -1;
    if(act<7){
      int lo = (act>0)?5:0;
      float kw;
      selrange(ep1, lo, L, ksel, kw);
      fillRole(c,1,ksel,kw,lind,snode,processed,1);
    }
    if(act<5){
      int vsel; float vw;
      if(act==0 && (ksel/5)==0){
        selrange(ep2, 0, 5, vsel, vw);
      } else {
        int lo = (act>0)?5:0;
        selrange(ep2, lo, L, vsel, vw);
      }
      fillRole(c,2,vsel,vw,lind,snode,processed,(act!=1)?1:0);
    }

    for(int r2=0;r2<3;r2++){
      ERole er = g_erole[c][r2];
      if(er.enabled && er.op!=4){
        int ac = (er.op==0)?1:((er.op==1)?2:0);
        setGemm(c, r2, 13+r2, 0, er.e, 0, er.e, ac, -1, 10+r2, er.w);
      }
    }

    int cw = c*4;
    if(act==0){
      setGemm(c,3,19,1,cw+0,1,cw+0,0,-1,16,1.f);
      setGemm(c,4,11,1,cw+1,1,cw+1,0,-1,17,1.f);
      setGemm(c,5,12,1,cw+2,1,cw+2,0,-1,18,1.f);
      setGemm(c,6,20,1,cw+3,1,cw+3,0,10,2+c,aw);
    } else if(act==1){
      setGemm(c,3,10,1,cw+0,1,cw+0,2,-1,16,1.f);
      setGemm(c,4,11,1,cw+1,1,cw+1,0,-1,17,1.f);
      setGemm(c,6,16,1,cw+3,1,cw+3,0,10,2+c,aw);
      g_gd[c][6].mul=1; g_gd[c][6].srcA[1]=17;
    } else if(act==3){
      setGemm(c,3,10,1,cw+0,-1,0,1,-1,16,1.f);
      g_gd[c][3].nterms=3;
      g_gd[c][3].srcA[1]=11; g_gd[c][3].srcA[2]=12;
      g_gd[c][3].wKind[1]=1; g_gd[c][3].wIdx[1]=cw+1;
      g_gd[c][3].wKind[2]=1; g_gd[c][3].wIdx[2]=cw+2;
      setGemm(c,6,16,1,cw+3,1,cw+3,0,10,2+c,aw);
    } else if(act==5){
      setGemm(c,3,11,1,cw+1,1,cw+1,2,-1,16,1.f);
    }

    lind += nsrc;
  }
  g_rem_mask = (~processed) & 0xFF;
}

// ---------------- weight conversion: fp32 [k][n] -> bf16 hi/lo transposed [n][k] ----------------
__global__ void convw_kernel(const float* __restrict__ eW, const float* __restrict__ nW){
  __shared__ float tile[32][33];
  int w = blockIdx.z;
  const float* src = (w<34) ? eW + (size_t)w*262144 : nW + (size_t)(w-34)*262144;
  int k0 = blockIdx.x*32, n0 = blockIdx.y*32;
  int tr = threadIdx.x>>3;
  int tc = (threadIdx.x&7)*4;
  float4 v = *(const float4*)(src + (size_t)(k0+tr)*512 + n0+tc);
  tile[tr][tc+0]=v.x; tile[tr][tc+1]=v.y; tile[tr][tc+2]=v.z; tile[tr][tc+3]=v.w;
  __syncthreads();
  int nr = threadIdx.x>>3;       // row of transposed tile (n)
  int kc = (threadIdx.x&7)*4;    // col (k)
  union { __nv_bfloat16 b[4]; uint2 u; } ph, pl;
  #pragma unroll
  for(int j=0;j<4;j++){
    float x = tile[kc+j][nr];
    __nv_bfloat16 h = __float2bfloat16(x);
    ph.b[j] = h;
    pl.b[j] = __float2bfloat16(x - __bfloat162float(h));
  }
  size_t off = (size_t)w*262144 + (size_t)(n0+nr)*512 + k0+kc;
  *(uint2*)(g_Wth + off) = ph.u;
  *(uint2*)(g_Wtl + off) = pl.u;
}

// ---------------- edge prep ----------------
__global__ void prep_kernel(int c, const float* __restrict__ inpute, const float* __restrict__ inputo,
                            const float* __restrict__ edge_g, const float* __restrict__ edge_beta){
  int role = blockIdx.z;
  ERole er = g_erole[c][role];
  if(!er.enabled) return;
  int row = blockIdx.x;
  int t = threadIdx.x;
  const float* x = bufPtrC(er.src, inpute, inputo) + (size_t)row*DIM;
  if(er.op==4){
    float* d = g_qkv[role] + (size_t)row*DIM;
    d[t]     = er.w*x[t];
    d[t+256] = er.w*x[t+256];
    return;
  }
  float* d = g_prep[role] + (size_t)row*DIM;
  float a = x[t], b = x[t+256];
  if(er.op==3){ d[t]=a; d[t+256]=b; return; }
  float s  = blockReduceSum(a+b);
  float mean = s*(1.f/512.f);
  float da=a-mean, db=b-mean;
  float s2 = blockReduceSum(da*da+db*db);
  float rstd = rsqrtf(s2*(1.f/512.f)+1e-6f);
  const float* g  = edge_g    + (size_t)er.e*DIM;
  const float* be = edge_beta + (size_t)er.e*DIM;
  d[t]     = da*rstd*g[t]     + be[t];
  d[t+256] = db*rstd*g[t+256] + be[t+256];
}

// ---------------- LN(q) for MHA ----------------
__global__ void lnq_kernel(int c, const float* __restrict__ node_g, const float* __restrict__ node_beta){
  if(g_node_act[c]!=0) return;
  int row=blockIdx.x, t=threadIdx.x;
  const float* x = g_qkv[0] + (size_t)row*DIM;
  float a=x[t], b=x[t+256];
  float s = blockReduceSum(a+b);
  float mean = s*(1.f/512.f);
  float da=a-mean, db=b-mean;
  float s2 = blockReduceSum(da*da+db*db);
  float rstd = rsqrtf(s2*(1.f/512.f)+1e-6f);
  const float* g  = node_g    + (size_t)c*DIM;
  const float* be = node_beta + (size_t)c*DIM;
  g_lnq[(size_t)row*DIM+t]     = da*rstd*g[t]     + be[t];
  g_lnq[(size_t)row*DIM+t+256] = db*rstd*g[t+256] + be[t+256];
}

// ---------------- tensor-core GEMM ----------------
// dst = scale*(res + act(sum_t A_t@W_t + b)), A split to bf16 hi/lo on the fly,
// W pre-split. Computes Ah@Wh + Ah@Wl + Al@Wh with m16n8k16 bf16 mma.
#define SMS 40          // smem row stride in bf16 elems (32 data + 8 pad)
#define BUFE (128*SMS)  // 5120 elems per buffer

__device__ __forceinline__ void mma16816(float* c, uint32_t a0,uint32_t a1,uint32_t a2,uint32_t a3,
                                         uint32_t b0, uint32_t b1){
  asm volatile("mma.sync.aligned.m16n8k16.row.col.f32.bf16.bf16.f32 "
    "{%0,%1,%2,%3}, {%4,%5,%6,%7}, {%8,%9}, {%0,%1,%2,%3};"
    : "+f"(c[0]),"+f"(c[1]),"+f"(c[2]),"+f"(c[3])
    : "r"(a0),"r"(a1),"r"(a2),"r"(a3),"r"(b0),"r"(b1));
}

__global__ void __launch_bounds__(256,1) gemm_kernel(int c,int slotBase,
  const float* __restrict__ inpute,const float* __restrict__ inputo,
  const float* __restrict__ edge_b,const float* __restrict__ node_b)
{
  GemmDesc gd = g_gd[c][slotBase + blockIdx.z];
  if(!gd.enabled) return;
  extern __shared__ __nv_bfloat16 sm[];
  __nv_bfloat16* Ah = sm;
  __nv_bfloat16* Al = sm + 2*BUFE;
  __nv_bfloat16* Bh = sm + 4*BUFE;
  __nv_bfloat16* Bl = sm + 6*BUFE;

  const int rowBase = blockIdx.y*128;
  const int colBase = blockIdx.x*128;
  const int tid = threadIdx.x;
  const int lane = tid & 31;
  const int wid = tid >> 5;
  const int wr = wid >> 2;       // 0..1 (64-row half)
  const int wc = wid & 3;        // 0..3 (32-col quarter)
  const int g8 = lane >> 2;      // 0..7
  const int tg = lane & 3;       // 0..3

  // per-term pointers
  const float* Aterm[3];
  const __nv_bfloat16* Whp[3];
  const __nv_bfloat16* Wlp[3];
  for(int t=0;t<gd.nterms;t++){
    Aterm[t] = bufPtrC(gd.srcA[t],inpute,inputo);
    int wg = gd.wKind[t] ? (34+gd.wIdx[t]) : gd.wIdx[t];
    Whp[t] = g_Wth + (size_t)wg*262144;
    Wlp[t] = g_Wtl + (size_t)wg*262144;
  }
  const float* A2 = gd.mul ? bufPtrC(gd.srcA[1],inpute,inputo) : nullptr;

  float acc[4][4][4];
  #pragma unroll
  for(int i=0;i<4;i++)
    #pragma unroll
    for(int j=0;j<4;j++)
      #pragma unroll
      for(int q=0;q<4;q++) acc[i][j][q]=0.f;

  // loader coords
  const int arL = (tid>>3);        // + it*32 -> row
  const int akL = (tid&7)*4;       // k within chunk
  const int bnL = (tid>>2);        // + p*64 -> n
  const int bkL = (tid&3)*8;       // k within chunk

  float4 pa[4]; uint4 pbh[2], pbl[2];
  const int totalChunks = gd.nterms*16;

  // ---- load chunk 0
  {
    const float* A = Aterm[0];
    #pragma unroll
    for(int it=0;it<4;it++){
      int r = arL + it*32;
      pa[it] = *(const float4*)(A + (size_t)(rowBase+r)*512 + akL);
      if(A2){
        float4 u = *(const float4*)(A2 + (size_t)(rowBase+r)*512 + akL);
        pa[it].x*=u.x; pa[it].y*=u.y; pa[it].z*=u.z; pa[it].w*=u.w;
      }
    }
    #pragma unroll
    for(int p=0;p<2;p++){
      int n = bnL + p*64;
      pbh[p] = *(const uint4*)(Whp[0] + (size_t)(colBase+n)*512 + bkL);
      pbl[p] = *(const uint4*)(Wlp[0] + (size_t)(colBase+n)*512 + bkL);
    }
  }
  // store chunk 0 -> buf 0
  {
    #pragma unroll
    for(int it=0;it<4;it++){
      int r = arL + it*32;
      union { __nv_bfloat16 b[4]; uint2 u; } ph, pl;
      float xs[4]={pa[it].x,pa[it].y,pa[it].z,pa[it].w};
      #pragma unroll
      for(int j=0;j<4;j++){
        __nv_bfloat16 h = __float2bfloat16(xs[j]);
        ph.b[j]=h; pl.b[j]=__float2bfloat16(xs[j]-__bfloat162float(h));
      }
      *(uint2*)(Ah + r*SMS + akL) = ph.u;
      *(uint2*)(Al + r*SMS + akL) = pl.u;
    }
    #pragma unroll
    for(int p=0;p<2;p++){
      int n = bnL + p*64;
      *(uint2*)(Bh + n*SMS + bkL)     = make_uint2(pbh[p].x, pbh[p].y);
      *(uint2*)(Bh + n*SMS + bkL + 4) = make_uint2(pbh[p].z, pbh[p].w);
      *(uint2*)(Bl + n*SMS + bkL)     = make_uint2(pbl[p].x, pbl[p].y);
      *(uint2*)(Bl + n*SMS + bkL + 4) = make_uint2(pbl[p].z, pbl[p].w);
    }
  }
  __syncthreads();

  int buf = 0;
  for(int ch=1; ch<=totalChunks; ch++){
    // prefetch next chunk
    if(ch<totalChunks){
      int term = ch>>4; int k0 = (ch&15)*32;
      const float* A = Aterm[term];
      #pragma unroll
      for(int it=0;it<4;it++){
        int r = arL + it*32;
        pa[it] = *(const float4*)(A + (size_t)(rowBase+r)*512 + k0 + akL);
        if(A2){
          float4 u = *(const float4*)(A2 + (size_t)(rowBase+r)*512 + k0 + akL);
          pa[it].x*=u.x; pa[it].y*=u.y; pa[it].z*=u.z; pa[it].w*=u.w;
        }
      }
      #pragma unroll
      for(int p=0;p<2;p++){
        int n = bnL + p*64;
        pbh[p] = *(const uint4*)(Whp[term] + (size_t)(colBase+n)*512 + k0 + bkL);
        pbl[p] = *(const uint4*)(Wlp[term] + (size_t)(colBase+n)*512 + k0 + bkL);
      }
    }
    // compute current buf
    {
      const __nv_bfloat16* ah_ = Ah + buf*BUFE;
      const __nv_bfloat16* al_ = Al + buf*BUFE;
      const __nv_bfloat16* bh_ = Bh + buf*BUFE;
      const __nv_bfloat16* bl_ = Bl + buf*BUFE;
      #pragma unroll
      for(int kk=0;kk<32;kk+=16){
        uint32_t bh0[4],bh1[4],bl0[4],bl1[4];
        #pragma unroll
        for(int nb=0;nb<4;nb++){
          int o = (wc*32+nb*8+g8)*SMS + kk + tg*2;
          bh0[nb]=*(const uint32_t*)(bh_+o); bh1[nb]=*(const uint32_t*)(bh_+o+8);
          bl0[nb]=*(const uint32_t*)(bl_+o); bl1[nb]=*(const uint32_t*)(bl_+o+8);
        }
        #pragma unroll
        for(int mb=0;mb<4;mb++){
          int o = (wr*64+mb*16+g8)*SMS + kk + tg*2;
          uint32_t ah0=*(const uint32_t*)(ah_+o);
          uint32_t ah1=*(const uint32_t*)(ah_+o+8*SMS);
          uint32_t ah2=*(const uint32_t*)(ah_+o+8);
          uint32_t ah3=*(const uint32_t*)(ah_+o+8*SMS+8);
          uint32_t al0=*(const uint32_t*)(al_+o);
          uint32_t al1=*(const uint32_t*)(al_+o+8*SMS);
          uint32_t al2=*(const uint32_t*)(al_+o+8);
          uint32_t al3=*(const uint32_t*)(al_+o+8*SMS+8);
          #pragma unroll
          for(int nb=0;nb<4;nb++){
            mma16816(acc[mb][nb], ah0,ah1,ah2,ah3, bh0[nb],bh1[nb]);
            mma16816(acc[mb][nb], ah0,ah1,ah2,ah3, bl0[nb],bl1[nb]);
            mma16816(acc[mb][nb], al0,al1,al2,al3, bh0[nb],bh1[nb]);
          }
        }
      }
    }
    // store prefetched -> other buf
    if(ch<totalChunks){
      int nb2 = buf^1;
      #pragma unroll
      for(int it=0;it<4;it++){
        int r = arL + it*32;
        union { __nv_bfloat16 b[4]; uint2 u; } ph, pl;
        float xs[4]={pa[it].x,pa[it].y,pa[it].z,pa[it].w};
        #pragma unroll
        for(int j=0;j<4;j++){
          __nv_bfloat16 h = __float2bfloat16(xs[j]);
          ph.b[j]=h; pl.b[j]=__float2bfloat16(xs[j]-__bfloat162float(h));
        }
        *(uint2*)(Ah + nb2*BUFE + r*SMS + akL) = ph.u;
        *(uint2*)(Al + nb2*BUFE + r*SMS + akL) = pl.u;
      }
      #pragma unroll
      for(int p=0;p<2;p++){
        int n = bnL + p*64;
        *(uint2*)(Bh + nb2*BUFE + n*SMS + bkL)     = make_uint2(pbh[p].x, pbh[p].y);
        *(uint2*)(Bh + nb2*BUFE + n*SMS + bkL + 4) = make_uint2(pbh[p].z, pbh[p].w);
        *(uint2*)(Bl + nb2*BUFE + n*SMS + bkL)     = make_uint2(pbl[p].x, pbl[p].y);
        *(uint2*)(Bl + nb2*BUFE + n*SMS + bkL + 4) = make_uint2(pbl[p].z, pbl[p].w);
      }
      __syncthreads();
      buf = nb2;
    }
  }

  // ---- epilogue
  const float* bias = nullptr;
  if(gd.bKind==0)      bias = edge_b + (size_t)gd.bIdx*512;
  else if(gd.bKind==1) bias = node_b + (size_t)gd.bIdx*512;
  const float* res = (gd.resBuf>=0)? bufPtrC(gd.resBuf,inpute,inputo) : nullptr;
  float* dst = bufPtrM(gd.dstBuf);
  #pragma unroll
  for(int mb=0;mb<4;mb++){
    #pragma unroll
    for(int nb=0;nb<4;nb++){
      int row0 = rowBase + wr*64 + mb*16 + g8;
      int col0 = colBase + wc*32 + nb*8 + tg*2;
      #pragma unroll
      for(int half=0; half<2; half++){
        int row = row0 + half*8;
        float z0 = acc[mb][nb][half*2+0] + (bias? bias[col0]:0.f);
        float z1 = acc[mb][nb][half*2+1] + (bias? bias[col0+1]:0.f);
        if(gd.actCode==1){ z0=fmaxf(z0,0.f); z1=fmaxf(z1,0.f); }
        else if(gd.actCode==2){ z0=geluf(z0); z1=geluf(z1); }
        if(res){
          float2 rv = *(const float2*)(res + (size_t)row*512 + col0);
          z0 += rv.x; z1 += rv.y;
        }
        float2 ov; ov.x = gd.scale*z0; ov.y = gd.scale*z1;
        *(float2*)(dst + (size_t)row*512 + col0) = ov;
      }
    }
  }
}

// ---------------- flash attention (B=4,H=8,S=1024,dh=64) ----------------
__global__ void __launch_bounds__(256) attn_kernel(int c){
  if(g_node_act[c]!=0) return;
  __shared__ float qs[64][65];
  __shared__ float ks[32][65];
  __shared__ float vs[32][65];
  __shared__ float ps[64][33];
  int tid = threadIdx.x;
  int bh = blockIdx.y; int b = bh>>3, h = bh&7;
  int s0 = blockIdx.x*64;
  const float* Q = g_tt[0]; const float* K = g_tt[1]; const float* V = g_tt[2];
  size_t baseQ = ((size_t)(b*1024 + s0))*DIM + h*64;
  #pragma unroll
  for(int i=0;i<16;i++){
    int e = tid + i*256; int rr = e>>6; int dd = e&63;
    qs[rr][dd] = Q[baseQ + (size_t)rr*DIM + dd];
  }
  int rg = tid>>4, kg = tid&15;
  float acc[4][4]; float m_prev[4], lsum[4];
  #pragma unroll
  for(int i=0;i<4;i++){
    m_prev[i]=-1e30f; lsum[i]=0.f;
    #pragma unroll
    for(int j=0;j<4;j++) acc[i][j]=0.f;
  }
  for(int kt=0;kt<32;kt++){
    __syncthreads();
    size_t baseK = ((size_t)(b*1024 + kt*32))*DIM + h*64;
    #pragma unroll
    for(int i=0;i<8;i++){
      int e = tid + i*256; int rr = e>>6; int dd = e&63;
      ks[rr][dd] = K[baseK + (size_t)rr*DIM + dd];
      vs[rr][dd] = V[baseK + (size_t)rr*DIM + dd];
    }
    __syncthreads();
    float sc[4][2];
    #pragma unroll
    for(int i=0;i<4;i++){ sc[i][0]=0.f; sc[i][1]=0.f; }
    #pragma unroll 4
    for(int d=0;d<64;d++){
      float rk0 = ks[kg*2+0][d], rk1 = ks[kg*2+1][d];
      #pragma unroll
      for(int i=0;i<4;i++){
        float rq = qs[rg*4+i][d];
        sc[i][0] = fmaf(rq,rk0,sc[i][0]);
        sc[i][1] = fmaf(rq,rk1,sc[i][1]);
      }
    }
    #pragma unroll
    for(int i=0;i<4;i++){
      float s0v = sc[i][0]*0.125f, s1v = sc[i][1]*0.125f;
      float mloc = fmaxf(s0v,s1v);
      #pragma unroll
      for(int o=1;o<16;o<<=1) mloc = fmaxf(mloc, __shfl_xor_sync(0xffffffffu,mloc,o));
      float m_new = fmaxf(m_prev[i], mloc);
      float p0 = __expf(s0v-m_new), p1 = __expf(s1v-m_new);
      ps[rg*4+i][kg*2+0]=p0; ps[rg*4+i][kg*2+1]=p1;
      float lloc = p0+p1;
      #pragma unroll
      for(int o=1;o<16;o<<=1) lloc += __shfl_xor_sync(0xffffffffu,lloc,o);
      float corr = __expf(m_prev[i]-m_new);
      lsum[i] = lsum[i]*corr + lloc;
      m_prev[i] = m_new;
      #pragma unroll
      for(int j=0;j<4;j++) acc[i][j]*=corr;
    }
    __syncthreads();
    #pragma unroll 4
    for(int j=0;j<32;j++){
      float v0=vs[j][kg*4+0], v1=vs[j][kg*4+1], v2=vs[j][kg*4+2], v3=vs[j][kg*4+3];
      #pragma unroll
      for(int i=0;i<4;i++){
        float p = ps[rg*4+i][j];
        acc[i][0]=fmaf(p,v0,acc[i][0]); acc[i][1]=fmaf(p,v1,acc[i][1]);
        acc[i][2]=fmaf(p,v2,acc[i][2]); acc[i][3]=fmaf(p,v3,acc[i][3]);
      }
    }
  }
  #pragma unroll
  for(int i=0;i<4;i++){
    float inv = 1.f/lsum[i];
    size_t o = ((size_t)(b*1024 + s0 + rg*4 + i))*DIM + h*64 + kg*4;
    g_attn[o+0]=acc[i][0]*inv; g_attn[o+1]=acc[i][1]*inv;
    g_attn[o+2]=acc[i][2]*inv; g_attn[o+3]=acc[i][3]*inv;
  }
}

// ---------------- elementwise node ops (acts 2,4,5,6,7) ----------------
__global__ void post_elt(int c, const float* __restrict__ node_g, const float* __restrict__ node_beta){
  int act = g_node_act[c];
  if(act==0||act==1||act==3) return;
  float aw = g_node_aw[c];
  int row=blockIdx.x, t=threadIdx.x;
  size_t off=(size_t)row*DIM;
  const float* q=g_qkv[0]+off; const float* k=g_qkv[1]+off; const float* v=g_qkv[2]+off;
  float* o = g_outbuf[c]+off;
  if(act==4){
    o[t]     = aw*(q[t]*sigmoidf(k[t]) + v[t]);
    o[t+256] = aw*(q[t+256]*sigmoidf(k[t+256]) + v[t+256]);
    return;
  }
  if(act==5){
    const float* tt = g_tt[0]+off;
    o[t]=aw*(q[t]+tt[t]); o[t+256]=aw*(q[t+256]+tt[t+256]);
    return;
  }
  if(act==6){
    o[t]=aw*(q[t]+k[t]); o[t+256]=aw*(q[t+256]+k[t+256]);
    return;
  }
  float a,b;
  if(act==2){ a=q[t]+k[t]+v[t]; b=q[t+256]+k[t+256]+v[t+256]; }
  else      { a=q[t];           b=q[t+256]; }
  float s = blockReduceSum(a+b);
  float mean = s*(1.f/512.f);
  float da=a-mean, db=b-mean;
  float s2 = blockReduceSum(da*da+db*db);
  float rstd = rsqrtf(s2*(1.f/512.f)+1e-6f);
  const float* g  = node_g    + (size_t)c*DIM;
  const float* be = node_beta + (size_t)c*DIM;
  o[t]     = aw*(da*rstd*g[t]     + be[t]);
  o[t+256] = aw*(db*rstd*g[t+256] + be[t+256]);
}

// ---------------- final: sum remaining nodes + LN ----------------
__global__ void final_kernel(const float* __restrict__ og, const float* __restrict__ obe, float* __restrict__ out){
  int row=blockIdx.x, t=threadIdx.x;
  int mask = g_rem_mask;
  size_t off=(size_t)row*DIM;
  float a=0.f, b=0.f;
  #pragma unroll
  for(int i=0;i<8;i++) if((mask>>i)&1){
    a += g_outbuf[i][off+t];
    b += g_outbuf[i][off+t+256];
  }
  float s = blockReduceSum(a+b);
  float mean = s*(1.f/512.f);
  float da=a-mean, db=b-mean;
  float s2 = blockReduceSum(da*da+db*db);
  float rstd = rsqrtf(s2*(1.f/512.f)+1e-6f);
  out[off+t]     = da*rstd*og[t]     + obe[t];
  out[off+t+256] = db*rstd*og[t+256] + obe[t+256];
}

extern "C" void kernel_launch(void* const* d_in, const int* in_sizes, int n_in,
                              void* d_out, int out_size) {
  (void)in_sizes; (void)n_in; (void)out_size;
  const float* inpute    = (const float*)d_in[0];
  const float* inputo    = (const float*)d_in[1];
  const float* node_p    = (const float*)d_in[2];
  const float* edge_p    = (const float*)d_in[3];
  const float* edge_W    = (const float*)d_in[4];
  const float* edge_b    = (const float*)d_in[5];
  const float* edge_g    = (const float*)d_in[6];
  const float* edge_beta = (const float*)d_in[7];
  const float* node_W    = (const float*)d_in[8];
  const float* node_b    = (const float*)d_in[9];
  const float* node_g    = (const float*)d_in[10];
  const float* node_beta = (const float*)d_in[11];
  const float* out_g     = (const float*)d_in[12];
  const float* out_beta  = (const float*)d_in[13];
  float* out = (float*)d_out;

  const int gemmSmem = 8*BUFE*(int)sizeof(__nv_bfloat16); // 81920 bytes
  cudaFuncSetAttribute(gemm_kernel, cudaFuncAttributeMaxDynamicSharedMemorySize, gemmSmem);

  route_kernel<<<1,1>>>(node_p, edge_p);
  convw_kernel<<<dim3(16,16,66),256>>>(edge_W, node_W);
  for(int c=0;c<8;c++){
    prep_kernel<<<dim3(NROWS,1,3),256>>>(c, inpute, inputo, edge_g, edge_beta);
    gemm_kernel<<<dim3(4,32,3),256,gemmSmem>>>(c,0,inpute,inputo,edge_b,node_b);
    lnq_kernel<<<NROWS,256>>>(c, node_g, node_beta);
    gemm_kernel<<<dim3(4,32,3),256,gemmSmem>>>(c,3,inpute,inputo,edge_b,node_b);
    attn_kernel<<<dim3(16,32),256>>>(c);
    gemm_kernel<<<dim3(4,32,1),256,gemmSmem>>>(c,6,inpute,inputo,edge_b,node_b);
    post_elt<<<NROWS,256>>>(c, node_g, node_beta);
  }
  final_kernel<<<NROWS,256>>>(out_g, out_beta, out);
}